// round 6
// baseline (speedup 1.0000x reference)
#include <cuda_runtime.h>
#include <stdint.h>

// Problem constants (fixed for GCN_69097433858735)
#define NN 100000
#define EE 3200000
#define FIN 128
#define HH 16
#define CC 2

// Static scratch (zero-initialized at module load; g_cnt zero-invariant is
// maintained across calls: k_dinv re-zeroes it after consuming it)
__device__ int   g_cnt [NN];                     // in-degree (edges only)
__device__ float g_dinv[NN];                     // rsqrt(deg+1)
__device__ __align__(16) float g_hs  [NN * HH];  // (x@W1) * dinv[n]
__device__ __align__(16) float g_acc1[NN * HH];
__device__ __align__(16) float g_gs  [NN * CC];  // (relu_out @ W2) * dinv[n]
__device__ __align__(16) float g_acc2[NN * CC];

// 1) count in-degrees from dst half (edge_index is int32; JAX x64 disabled).
//    int4-vectorized: 4 edges per thread.
__global__ void k_count(const int* __restrict__ ei, int e) {
    int i4 = blockIdx.x * blockDim.x + threadIdx.x;
    int base = i4 * 4;
    if (base >= e) return;
    const int* dstp = ei + e;
    if (base + 3 < e) {
        int4 d4 = *(const int4*)(dstp + base);   // dst half is 16B-aligned (e%4==0)
        int a = d4.x, b = d4.y, c = d4.z, d = d4.w;
        if ((unsigned)a >= NN) a = 0;
        if ((unsigned)b >= NN) b = 0;
        if ((unsigned)c >= NN) c = 0;
        if ((unsigned)d >= NN) d = 0;
        atomicAdd(&g_cnt[a], 1);
        atomicAdd(&g_cnt[b], 1);
        atomicAdd(&g_cnt[c], 1);
        atomicAdd(&g_cnt[d], 1);
    } else {
        for (int i = base; i < e; i++) {
            int d = dstp[i];
            if ((unsigned)d >= NN) d = 0;
            atomicAdd(&g_cnt[d], 1);
        }
    }
}

// 2) dinv = rsqrt(deg+1), and restore the zero-invariant on g_cnt
__global__ void k_dinv(int n) {
    int i = blockIdx.x * blockDim.x + threadIdx.x;
    if (i < n) {
        g_dinv[i] = rsqrtf((float)(g_cnt[i] + 1));
        g_cnt[i] = 0;   // ready for next graph replay
    }
}

// 3) hs[n] = (x[n] @ W1) * dinv[n]; zero acc1[n].
//    2 threads per row: each handles 64 K-elements, combined via shfl.
__global__ __launch_bounds__(256) void k_gemm1(const float* __restrict__ x,
                                               const float* __restrict__ W1,
                                               int n) {
    __shared__ float sW1[FIN * HH];  // 8 KB
    for (int i = threadIdx.x; i < FIN * HH; i += blockDim.x)
        sW1[i] = W1[i];
    __syncthreads();

    int t = blockIdx.x * blockDim.x + threadIdx.x;
    int row  = t >> 1;
    int half = t & 1;
    if (row >= n) return;

    float acc[HH];
#pragma unroll
    for (int j = 0; j < HH; j++) acc[j] = 0.0f;

    const float4* xr = (const float4*)(x + (long long)row * FIN) + half * 16;
    const float*  w  = sW1 + half * 64 * HH;
#pragma unroll 8
    for (int k4 = 0; k4 < 16; k4++) {
        float4 xv = __ldg(&xr[k4]);
        int k = k4 * 4;
#pragma unroll
        for (int j = 0; j < HH; j++) {
            acc[j] += xv.x * w[(k + 0) * HH + j];
            acc[j] += xv.y * w[(k + 1) * HH + j];
            acc[j] += xv.z * w[(k + 2) * HH + j];
            acc[j] += xv.w * w[(k + 3) * HH + j];
        }
    }
    // combine the two K-halves (partner lane differs only in bit 0)
#pragma unroll
    for (int j = 0; j < HH; j++)
        acc[j] += __shfl_xor_sync(0xffffffffu, acc[j], 1);

    float di = g_dinv[row];
    float4* hs4 = (float4*)(g_hs   + (long long)row * HH);
    float4* ac4 = (float4*)(g_acc1 + (long long)row * HH);
    float4 z = make_float4(0.f, 0.f, 0.f, 0.f);
#pragma unroll
    for (int q = 0; q < 2; q++) {
        int qq = half * 2 + q;      // each thread writes 2 of the 4 float4s
        float4 v;
        v.x = acc[qq * 4 + 0] * di;
        v.y = acc[qq * 4 + 1] * di;
        v.z = acc[qq * 4 + 2] * di;
        v.w = acc[qq * 4 + 3] * di;
        hs4[qq] = v;
        ac4[qq] = z;
    }
}

// 4) scatter layer 1: acc1[dst] += hs[src]  (4x float4 atomicAdd -> RED)
__global__ __launch_bounds__(256) void k_scatter1(const int* __restrict__ ei, int e) {
    int i = blockIdx.x * blockDim.x + threadIdx.x;
    if (i >= e) return;
    int s = ei[i];
    int d = ei[e + i];
    if ((unsigned)s >= NN) s = 0;
    if ((unsigned)d >= NN) d = 0;
    const float4* hs4 = (const float4*)(g_hs + (long long)s * HH);
    float4* ap = (float4*)(g_acc1 + (long long)d * HH);
    float4 v0 = __ldg(&hs4[0]);
    float4 v1 = __ldg(&hs4[1]);
    float4 v2 = __ldg(&hs4[2]);
    float4 v3 = __ldg(&hs4[3]);
    atomicAdd(ap + 0, v0);
    atomicAdd(ap + 1, v1);
    atomicAdd(ap + 2, v2);
    atomicAdd(ap + 3, v3);
}

// 5) layer-1 epilogue + GEMM2: out1 = relu(dinv*(acc1+hs) + b1);
//    gs = (out1 @ W2) * dinv; zero acc2
__global__ __launch_bounds__(256) void k_fin1_gemm2(const float* __restrict__ b1,
                                                    const float* __restrict__ W2,
                                                    int n) {
    __shared__ float sW2[HH * CC];
    __shared__ float sb1[HH];
    for (int i = threadIdx.x; i < HH * CC; i += blockDim.x) sW2[i] = W2[i];
    for (int i = threadIdx.x; i < HH; i += blockDim.x) sb1[i] = b1[i];
    __syncthreads();

    int row = blockIdx.x * blockDim.x + threadIdx.x;
    if (row >= n) return;
    float di = g_dinv[row];

    const float4* ac4 = (const float4*)(g_acc1 + (long long)row * HH);
    const float4* hs4 = (const float4*)(g_hs + (long long)row * HH);
    float gc0 = 0.f, gc1 = 0.f;
#pragma unroll
    for (int q = 0; q < HH / 4; q++) {
        float4 a = ac4[q];
        float4 h = hs4[q];
        float o0 = fmaxf(di * (a.x + h.x) + sb1[q * 4 + 0], 0.f);
        float o1 = fmaxf(di * (a.y + h.y) + sb1[q * 4 + 1], 0.f);
        float o2 = fmaxf(di * (a.z + h.z) + sb1[q * 4 + 2], 0.f);
        float o3 = fmaxf(di * (a.w + h.w) + sb1[q * 4 + 3], 0.f);
        gc0 += o0 * sW2[(q * 4 + 0) * CC + 0] + o1 * sW2[(q * 4 + 1) * CC + 0]
             + o2 * sW2[(q * 4 + 2) * CC + 0] + o3 * sW2[(q * 4 + 3) * CC + 0];
        gc1 += o0 * sW2[(q * 4 + 0) * CC + 1] + o1 * sW2[(q * 4 + 1) * CC + 1]
             + o2 * sW2[(q * 4 + 2) * CC + 1] + o3 * sW2[(q * 4 + 3) * CC + 1];
    }
    *(float2*)(g_gs   + (long long)row * CC) = make_float2(gc0 * di, gc1 * di);
    *(float2*)(g_acc2 + (long long)row * CC) = make_float2(0.f, 0.f);
}

// 6) scatter layer 2: acc2[dst] += gs[src]  (float2 atomicAdd)
__global__ __launch_bounds__(256) void k_scatter2(const int* __restrict__ ei, int e) {
    int i = blockIdx.x * blockDim.x + threadIdx.x;
    if (i >= e) return;
    int s = ei[i];
    int d = ei[e + i];
    if ((unsigned)s >= NN) s = 0;
    if ((unsigned)d >= NN) d = 0;
    float2 v = __ldg((const float2*)(g_gs + (long long)s * CC));
    atomicAdd((float2*)(g_acc2 + (long long)d * CC), v);
}

// 7) final: out = dinv*(acc2+gs) + b2
__global__ void k_final(const float* __restrict__ b2, float* __restrict__ out, int n) {
    int row = blockIdx.x * blockDim.x + threadIdx.x;
    if (row >= n) return;
    float di = g_dinv[row];
    float2 a = *((const float2*)(g_acc2 + (long long)row * CC));
    float2 h = *((const float2*)(g_gs + (long long)row * CC));
    float2 o;
    o.x = di * (a.x + h.x) + b2[0];
    o.y = di * (a.y + h.y) + b2[1];
    *((float2*)(out + (long long)row * CC)) = o;
}

extern "C" void kernel_launch(void* const* d_in, const int* in_sizes, int n_in,
                              void* d_out, int out_size) {
    const float* x  = (const float*)d_in[0];
    const int*   ei = (const int*)d_in[1];    // int32 (JAX x64 disabled)
    const float* W1 = (const float*)d_in[2];
    const float* b1 = (const float*)d_in[3];
    const float* W2 = (const float*)d_in[4];
    const float* b2 = (const float*)d_in[5];
    float* out = (float*)d_out;

    int n = in_sizes[0] / FIN;     // 100000
    int e = in_sizes[1] / 2;       // 3200000

    const int T = 256;
    int gb_n  = (n + T - 1) / T;
    int gb_e  = (e + T - 1) / T;
    int gb_e4 = (e / 4 + T - 1) / T;
    int gb_2n = (2 * n + T - 1) / T;

    k_count     <<<gb_e4, T>>>(ei, e);
    k_dinv      <<<gb_n, T>>>(n);
    k_gemm1     <<<gb_2n, T>>>(x, W1, n);
    k_scatter1  <<<gb_e, T>>>(ei, e);
    k_fin1_gemm2<<<gb_n, T>>>(b1, W2, n);
    k_scatter2  <<<gb_e, T>>>(ei, e);
    k_final     <<<gb_n, T>>>(b2, out, n);
}

// round 7
// speedup vs baseline: 1.2479x; 1.2479x over previous
#include <cuda_runtime.h>
#include <stdint.h>

// Problem constants (fixed for GCN_69097433858735)
#define NN 100000
#define EE 3200000
#define FIN 128
#define HH 16
#define CC 2

// Static scratch (zero-initialized at load; g_cnt zero-invariant restored by k_final)
__device__ int   g_cnt [NN];                     // in-degree (edges only)
__device__ float g_dinv[NN];                     // rsqrt(deg+1)
__device__ __align__(16) float g_hs  [NN * HH];  // (x@W1) * dinv[n]
__device__ __align__(16) float g_acc1[NN * HH];
__device__ __align__(16) float g_gs  [NN * CC];  // (relu_out @ W2) * dinv[n]
__device__ __align__(16) float g_acc2[NN * CC];

// 1) count in-degrees from dst half (edge_index is int32; JAX x64 disabled)
__global__ void k_count(const int* __restrict__ ei, int e) {
    int i = blockIdx.x * blockDim.x + threadIdx.x;
    if (i >= e) return;
    int d = ei[e + i];
    if ((unsigned)d >= NN) d = 0;
    atomicAdd(&g_cnt[d], 1);
}

// 2) hs[n] = (x[n] @ W1) * dinv[n]; zero acc1[n]; dinv computed+stored here.
//    2 threads per row: each handles 64 K-elements, combined via shfl.
__global__ __launch_bounds__(256) void k_gemm1(const float* __restrict__ x,
                                               const float* __restrict__ W1,
                                               int n) {
    __shared__ float sW1[FIN * HH];  // 8 KB
    for (int i = threadIdx.x; i < FIN * HH; i += blockDim.x)
        sW1[i] = W1[i];
    __syncthreads();

    int t = blockIdx.x * blockDim.x + threadIdx.x;
    int row  = t >> 1;
    int half = t & 1;
    if (row >= n) return;

    float acc[HH];
#pragma unroll
    for (int j = 0; j < HH; j++) acc[j] = 0.0f;

    const float4* xr = (const float4*)(x + (long long)row * FIN) + half * 16;
    const float*  w  = sW1 + half * 64 * HH;
#pragma unroll 8
    for (int k4 = 0; k4 < 16; k4++) {
        float4 xv = __ldg(&xr[k4]);
        int k = k4 * 4;
#pragma unroll
        for (int j = 0; j < HH; j++) {
            acc[j] += xv.x * w[(k + 0) * HH + j];
            acc[j] += xv.y * w[(k + 1) * HH + j];
            acc[j] += xv.z * w[(k + 2) * HH + j];
            acc[j] += xv.w * w[(k + 3) * HH + j];
        }
    }
    // combine the two K-halves (partner lane differs only in bit 0)
#pragma unroll
    for (int j = 0; j < HH; j++)
        acc[j] += __shfl_xor_sync(0xffffffffu, acc[j], 1);

    // fused dinv = rsqrt(deg+1); g_cnt stays valid until k_final re-zeroes it
    float di = rsqrtf((float)(g_cnt[row] + 1));
    if (half == 0) g_dinv[row] = di;

    float4* hs4 = (float4*)(g_hs   + (long long)row * HH);
    float4* ac4 = (float4*)(g_acc1 + (long long)row * HH);
    float4 z = make_float4(0.f, 0.f, 0.f, 0.f);
#pragma unroll
    for (int q = 0; q < 2; q++) {
        int qq = half * 2 + q;      // each thread writes 2 of the 4 float4s
        float4 v;
        v.x = acc[qq * 4 + 0] * di;
        v.y = acc[qq * 4 + 1] * di;
        v.z = acc[qq * 4 + 2] * di;
        v.w = acc[qq * 4 + 3] * di;
        hs4[qq] = v;
        ac4[qq] = z;
    }
}

// 3) scatter layer 1: acc1[dst] += hs[src]  — 4 THREADS PER EDGE.
//    Lanes 4k..4k+3 cooperate on edge k (8 edges/warp): one float4 each, so a
//    warp's gather/RED instruction touches 8 cache lines instead of 32.
__global__ __launch_bounds__(256) void k_scatter1(const int* __restrict__ ei, int e) {
    int gt   = blockIdx.x * blockDim.x + threadIdx.x;
    int lane = threadIdx.x & 31;
    int wbase = (gt >> 5) * 8;          // first edge of this warp
    int k = lane >> 2;                  // edge slot within warp (0..7)
    int q = lane & 3;                   // float4 slot within the 16-float row

    // coalesced index loads: lanes 0-7 load 8 src, lanes 8-15 load 8 dst
    int idx = wbase + (lane & 7);
    int tmp = 0;
    if (lane < 16 && idx < e)
        tmp = (lane < 8) ? ei[idx] : ei[e + idx];
    int s = __shfl_sync(0xffffffffu, tmp, k);
    int d = __shfl_sync(0xffffffffu, tmp, 8 + k);

    int eb = wbase + k;
    if (eb >= e) return;
    if ((unsigned)s >= NN) s = 0;
    if ((unsigned)d >= NN) d = 0;

    float4 v = __ldg((const float4*)(g_hs + (long long)s * HH) + q);
    atomicAdd((float4*)(g_acc1 + (long long)d * HH) + q, v);
}

// 4) layer-1 epilogue + GEMM2: out1 = relu(dinv*(acc1+hs) + b1);
//    gs = (out1 @ W2) * dinv; zero acc2
__global__ __launch_bounds__(256) void k_fin1_gemm2(const float* __restrict__ b1,
                                                    const float* __restrict__ W2,
                                                    int n) {
    __shared__ float sW2[HH * CC];
    __shared__ float sb1[HH];
    for (int i = threadIdx.x; i < HH * CC; i += blockDim.x) sW2[i] = W2[i];
    for (int i = threadIdx.x; i < HH; i += blockDim.x) sb1[i] = b1[i];
    __syncthreads();

    int row = blockIdx.x * blockDim.x + threadIdx.x;
    if (row >= n) return;
    float di = g_dinv[row];

    const float4* ac4 = (const float4*)(g_acc1 + (long long)row * HH);
    const float4* hs4 = (const float4*)(g_hs + (long long)row * HH);
    float gc0 = 0.f, gc1 = 0.f;
#pragma unroll
    for (int q = 0; q < HH / 4; q++) {
        float4 a = ac4[q];
        float4 h = hs4[q];
        float o0 = fmaxf(di * (a.x + h.x) + sb1[q * 4 + 0], 0.f);
        float o1 = fmaxf(di * (a.y + h.y) + sb1[q * 4 + 1], 0.f);
        float o2 = fmaxf(di * (a.z + h.z) + sb1[q * 4 + 2], 0.f);
        float o3 = fmaxf(di * (a.w + h.w) + sb1[q * 4 + 3], 0.f);
        gc0 += o0 * sW2[(q * 4 + 0) * CC + 0] + o1 * sW2[(q * 4 + 1) * CC + 0]
             + o2 * sW2[(q * 4 + 2) * CC + 0] + o3 * sW2[(q * 4 + 3) * CC + 0];
        gc1 += o0 * sW2[(q * 4 + 0) * CC + 1] + o1 * sW2[(q * 4 + 1) * CC + 1]
             + o2 * sW2[(q * 4 + 2) * CC + 1] + o3 * sW2[(q * 4 + 3) * CC + 1];
    }
    *(float2*)(g_gs   + (long long)row * CC) = make_float2(gc0 * di, gc1 * di);
    *(float2*)(g_acc2 + (long long)row * CC) = make_float2(0.f, 0.f);
}

// 5) scatter layer 2: acc2[dst] += gs[src]  (float2 atomicAdd)
__global__ __launch_bounds__(256) void k_scatter2(const int* __restrict__ ei, int e) {
    int i = blockIdx.x * blockDim.x + threadIdx.x;
    if (i >= e) return;
    int s = ei[i];
    int d = ei[e + i];
    if ((unsigned)s >= NN) s = 0;
    if ((unsigned)d >= NN) d = 0;
    float2 v = __ldg((const float2*)(g_gs + (long long)s * CC));
    atomicAdd((float2*)(g_acc2 + (long long)d * CC), v);
}

// 6) final: out = dinv*(acc2+gs) + b2; restore g_cnt zero-invariant
__global__ void k_final(const float* __restrict__ b2, float* __restrict__ out, int n) {
    int row = blockIdx.x * blockDim.x + threadIdx.x;
    if (row >= n) return;
    float di = g_dinv[row];
    float2 a = *((const float2*)(g_acc2 + (long long)row * CC));
    float2 h = *((const float2*)(g_gs + (long long)row * CC));
    float2 o;
    o.x = di * (a.x + h.x) + b2[0];
    o.y = di * (a.y + h.y) + b2[1];
    *((float2*)(out + (long long)row * CC)) = o;
    g_cnt[row] = 0;   // ready for next graph replay
}

extern "C" void kernel_launch(void* const* d_in, const int* in_sizes, int n_in,
                              void* d_out, int out_size) {
    const float* x  = (const float*)d_in[0];
    const int*   ei = (const int*)d_in[1];    // int32 (JAX x64 disabled)
    const float* W1 = (const float*)d_in[2];
    const float* b1 = (const float*)d_in[3];
    const float* W2 = (const float*)d_in[4];
    const float* b2 = (const float*)d_in[5];
    float* out = (float*)d_out;

    int n = in_sizes[0] / FIN;     // 100000
    int e = in_sizes[1] / 2;       // 3200000

    const int T = 256;
    int gb_n  = (n + T - 1) / T;
    int gb_e  = (e + T - 1) / T;
    int gb_2n = (2 * n + T - 1) / T;
    int gb_4e = ((long long)e * 4 + T - 1) / T;   // 4 threads per edge

    k_count     <<<gb_e, T>>>(ei, e);
    k_gemm1     <<<gb_2n, T>>>(x, W1, n);
    k_scatter1  <<<gb_4e, T>>>(ei, e);
    k_fin1_gemm2<<<gb_n, T>>>(b1, W2, n);
    k_scatter2  <<<gb_e, T>>>(ei, e);
    k_final     <<<gb_n, T>>>(b2, out, n);
}

// round 8
// speedup vs baseline: 1.3011x; 1.0426x over previous
#include <cuda_runtime.h>
#include <stdint.h>

// Problem constants (fixed for GCN_69097433858735)
#define NN 100000
#define EE 3200000
#define FIN 128
#define HH 16
#define CC 2
#define T 256

// Static scratch (zero-initialized at load; g_cnt zero-invariant restored by k_final)
__device__ int   g_cnt [NN];                     // in-degree (edges only)
__device__ float g_dinv[NN];                     // rsqrt(deg+1)
__device__ __align__(16) float g_h   [NN * HH];  // x@W1 (unscaled)
__device__ __align__(16) float g_hs  [NN * HH];  // h * dinv[n]
__device__ __align__(16) float g_acc1[NN * HH];
__device__ __align__(16) float g_gs  [NN * CC];  // (relu_out @ W2) * dinv[n]
__device__ __align__(16) float g_acc2[NN * CC];

// 1) FUSED: blocks [0, gemm_blocks) compute h = x@W1 (unscaled, 2 threads/row);
//    blocks [gemm_blocks, ...) count in-degrees from the dst half.
//    The two halves are independent and overlap on-chip.
__global__ __launch_bounds__(T) void k_fused(const float* __restrict__ x,
                                             const float* __restrict__ W1,
                                             const int* __restrict__ ei,
                                             int n, int e, int gemm_blocks) {
    if ((int)blockIdx.x >= gemm_blocks) {
        // ---- degree count part ----
        int i = (blockIdx.x - gemm_blocks) * T + threadIdx.x;
        if (i < e) {
            int d = ei[e + i];
            if ((unsigned)d >= NN) d = 0;
            atomicAdd(&g_cnt[d], 1);
        }
        return;
    }
    // ---- gemm part ----
    __shared__ float sW1[FIN * HH];  // 8 KB
    for (int i = threadIdx.x; i < FIN * HH; i += T)
        sW1[i] = W1[i];
    __syncthreads();

    int t    = blockIdx.x * T + threadIdx.x;
    int row  = t >> 1;
    int half = t & 1;
    if (row >= n) return;

    float acc[HH];
#pragma unroll
    for (int j = 0; j < HH; j++) acc[j] = 0.0f;

    const float4* xr = (const float4*)(x + (long long)row * FIN) + half * 16;
    const float*  w  = sW1 + half * 64 * HH;
#pragma unroll 8
    for (int k4 = 0; k4 < 16; k4++) {
        float4 xv = __ldg(&xr[k4]);
        int k = k4 * 4;
#pragma unroll
        for (int j = 0; j < HH; j++) {
            acc[j] += xv.x * w[(k + 0) * HH + j];
            acc[j] += xv.y * w[(k + 1) * HH + j];
            acc[j] += xv.z * w[(k + 2) * HH + j];
            acc[j] += xv.w * w[(k + 3) * HH + j];
        }
    }
#pragma unroll
    for (int j = 0; j < HH; j++)
        acc[j] += __shfl_xor_sync(0xffffffffu, acc[j], 1);

    float4* h4 = (float4*)(g_h + (long long)row * HH);
#pragma unroll
    for (int q = 0; q < 2; q++) {
        int qq = half * 2 + q;
        h4[qq] = make_float4(acc[qq * 4 + 0], acc[qq * 4 + 1],
                             acc[qq * 4 + 2], acc[qq * 4 + 3]);
    }
}

// 2) scale: dinv = rsqrt(cnt+1); hs = h*dinv; zero acc1.  4 threads per node.
__global__ __launch_bounds__(T) void k_scale(int n) {
    int t   = blockIdx.x * T + threadIdx.x;
    int row = t >> 2;
    int q   = t & 3;
    if (row >= n) return;
    float di = rsqrtf((float)(g_cnt[row] + 1));
    if (q == 0) g_dinv[row] = di;
    float4 h = *((const float4*)(g_h + (long long)row * HH) + q);
    h.x *= di; h.y *= di; h.z *= di; h.w *= di;
    *((float4*)(g_hs   + (long long)row * HH) + q) = h;
    *((float4*)(g_acc1 + (long long)row * HH) + q) = make_float4(0.f, 0.f, 0.f, 0.f);
}

// 3) scatter layer 1: acc1[dst] += hs[src]  — 4 threads per edge.
//    Lanes 4k..4k+3 cooperate on edge k (8 edges/warp): one float4 each, so a
//    warp's gather/RED instruction touches 8 cache lines instead of 32.
__global__ __launch_bounds__(T) void k_scatter1(const int* __restrict__ ei, int e) {
    int gt    = blockIdx.x * T + threadIdx.x;
    int lane  = threadIdx.x & 31;
    int wbase = (gt >> 5) * 8;          // first edge of this warp
    int k = lane >> 2;                  // edge slot within warp (0..7)
    int q = lane & 3;                   // float4 slot within the 16-float row

    // coalesced index loads: lanes 0-7 load 8 src, lanes 8-15 load 8 dst
    int idx = wbase + (lane & 7);
    int tmp = 0;
    if (lane < 16 && idx < e)
        tmp = (lane < 8) ? ei[idx] : ei[e + idx];
    int s = __shfl_sync(0xffffffffu, tmp, k);
    int d = __shfl_sync(0xffffffffu, tmp, 8 + k);

    int eb = wbase + k;
    if (eb >= e) return;
    if ((unsigned)s >= NN) s = 0;
    if ((unsigned)d >= NN) d = 0;

    float4 v = __ldg((const float4*)(g_hs + (long long)s * HH) + q);
    atomicAdd((float4*)(g_acc1 + (long long)d * HH) + q, v);
}

// 4) layer-1 epilogue + GEMM2: out1 = relu(dinv*(acc1+hs) + b1);
//    gs = (out1 @ W2) * dinv; zero acc2
__global__ __launch_bounds__(T) void k_fin1_gemm2(const float* __restrict__ b1,
                                                  const float* __restrict__ W2,
                                                  int n) {
    __shared__ float sW2[HH * CC];
    __shared__ float sb1[HH];
    for (int i = threadIdx.x; i < HH * CC; i += T) sW2[i] = W2[i];
    for (int i = threadIdx.x; i < HH; i += T) sb1[i] = b1[i];
    __syncthreads();

    int row = blockIdx.x * T + threadIdx.x;
    if (row >= n) return;
    float di = g_dinv[row];

    const float4* ac4 = (const float4*)(g_acc1 + (long long)row * HH);
    const float4* hs4 = (const float4*)(g_hs + (long long)row * HH);
    float gc0 = 0.f, gc1 = 0.f;
#pragma unroll
    for (int q = 0; q < HH / 4; q++) {
        float4 a = ac4[q];
        float4 h = hs4[q];
        float o0 = fmaxf(di * (a.x + h.x) + sb1[q * 4 + 0], 0.f);
        float o1 = fmaxf(di * (a.y + h.y) + sb1[q * 4 + 1], 0.f);
        float o2 = fmaxf(di * (a.z + h.z) + sb1[q * 4 + 2], 0.f);
        float o3 = fmaxf(di * (a.w + h.w) + sb1[q * 4 + 3], 0.f);
        gc0 += o0 * sW2[(q * 4 + 0) * CC + 0] + o1 * sW2[(q * 4 + 1) * CC + 0]
             + o2 * sW2[(q * 4 + 2) * CC + 0] + o3 * sW2[(q * 4 + 3) * CC + 0];
        gc1 += o0 * sW2[(q * 4 + 0) * CC + 1] + o1 * sW2[(q * 4 + 1) * CC + 1]
             + o2 * sW2[(q * 4 + 2) * CC + 1] + o3 * sW2[(q * 4 + 3) * CC + 1];
    }
    *(float2*)(g_gs   + (long long)row * CC) = make_float2(gc0 * di, gc1 * di);
    *(float2*)(g_acc2 + (long long)row * CC) = make_float2(0.f, 0.f);
}

// 5) scatter layer 2: acc2[dst] += gs[src]  (float2 atomicAdd)
__global__ __launch_bounds__(T) void k_scatter2(const int* __restrict__ ei, int e) {
    int i = blockIdx.x * T + threadIdx.x;
    if (i >= e) return;
    int s = ei[i];
    int d = ei[e + i];
    if ((unsigned)s >= NN) s = 0;
    if ((unsigned)d >= NN) d = 0;
    float2 v = __ldg((const float2*)(g_gs + (long long)s * CC));
    atomicAdd((float2*)(g_acc2 + (long long)d * CC), v);
}

// 6) final: out = dinv*(acc2+gs) + b2; restore g_cnt zero-invariant
__global__ void k_final(const float* __restrict__ b2, float* __restrict__ out, int n) {
    int row = blockIdx.x * blockDim.x + threadIdx.x;
    if (row >= n) return;
    float di = g_dinv[row];
    float2 a = *((const float2*)(g_acc2 + (long long)row * CC));
    float2 h = *((const float2*)(g_gs + (long long)row * CC));
    float2 o;
    o.x = di * (a.x + h.x) + b2[0];
    o.y = di * (a.y + h.y) + b2[1];
    *((float2*)(out + (long long)row * CC)) = o;
    g_cnt[row] = 0;   // ready for next graph replay
}

extern "C" void kernel_launch(void* const* d_in, const int* in_sizes, int n_in,
                              void* d_out, int out_size) {
    const float* x  = (const float*)d_in[0];
    const int*   ei = (const int*)d_in[1];    // int32 (JAX x64 disabled)
    const float* W1 = (const float*)d_in[2];
    const float* b1 = (const float*)d_in[3];
    const float* W2 = (const float*)d_in[4];
    const float* b2 = (const float*)d_in[5];
    float* out = (float*)d_out;

    int n = in_sizes[0] / FIN;     // 100000
    int e = in_sizes[1] / 2;       // 3200000

    int gb_n  = (n + T - 1) / T;
    int gb_e  = (e + T - 1) / T;
    int gb_gemm  = (2 * n + T - 1) / T;              // 782
    int gb_fused = gb_gemm + gb_e;                   // gemm blocks + count blocks
    int gb_4n = (4 * n + T - 1) / T;
    int gb_4e = (int)(((long long)e * 4 + T - 1) / T);

    k_fused     <<<gb_fused, T>>>(x, W1, ei, n, e, gb_gemm);
    k_scale     <<<gb_4n, T>>>(n);
    k_scatter1  <<<gb_4e, T>>>(ei, e);
    k_fin1_gemm2<<<gb_n, T>>>(b1, W2, n);
    k_scatter2  <<<gb_e, T>>>(ei, e);
    k_final     <<<gb_n, T>>>(b2, out, n);
}

// round 9
// speedup vs baseline: 1.3183x; 1.0132x over previous
#include <cuda_runtime.h>
#include <cuda_fp16.h>
#include <stdint.h>

// Problem constants (fixed for GCN_69097433858735)
#define NN 100000
#define EE 3200000
#define FIN 128
#define HH 16
#define CC 2
#define T 256

// Static scratch (zero-initialized at load; g_cnt zero-invariant restored by k_final)
__device__ int   g_cnt [NN];                      // in-degree (edges only)
__device__ float g_dinv[NN];                      // rsqrt(deg+1)
__device__ __align__(16) float  g_h   [NN * HH];  // x@W1 (unscaled)
__device__ __align__(16) float  g_hs  [NN * HH];  // h * dinv[n]  (fp32, for epilogue)
__device__ __align__(16) __half g_hsh [NN * HH];  // h * dinv[n]  (fp16, scatter payload)
__device__ __align__(16) float  g_acc1[NN * HH];
__device__ __align__(16) float  g_gs  [NN * CC];  // (relu_out @ W2) * dinv[n]
__device__ __align__(16) float  g_acc2[NN * CC];

// 1) FUSED: blocks [0, gemm_blocks) compute h = x@W1 (unscaled, 2 threads/row)
//    and zero acc1; blocks [gemm_blocks, ...) count in-degrees (4 edges/thread).
__global__ __launch_bounds__(T) void k_fused(const float* __restrict__ x,
                                             const float* __restrict__ W1,
                                             const int* __restrict__ ei,
                                             int n, int e, int gemm_blocks) {
    if ((int)blockIdx.x >= gemm_blocks) {
        // ---- degree count part: int4-vectorized over the dst half ----
        int base = ((blockIdx.x - gemm_blocks) * T + threadIdx.x) * 4;
        if (base >= e) return;
        const int* dstp = ei + e;
        if (base + 3 < e) {
            int4 d4 = *(const int4*)(dstp + base);
            int a = d4.x, b = d4.y, c = d4.z, d = d4.w;
            if ((unsigned)a >= NN) a = 0;
            if ((unsigned)b >= NN) b = 0;
            if ((unsigned)c >= NN) c = 0;
            if ((unsigned)d >= NN) d = 0;
            atomicAdd(&g_cnt[a], 1);
            atomicAdd(&g_cnt[b], 1);
            atomicAdd(&g_cnt[c], 1);
            atomicAdd(&g_cnt[d], 1);
        } else {
            for (int i = base; i < e; i++) {
                int d = dstp[i];
                if ((unsigned)d >= NN) d = 0;
                atomicAdd(&g_cnt[d], 1);
            }
        }
        return;
    }
    // ---- gemm part ----
    __shared__ float sW1[FIN * HH];  // 8 KB
    for (int i = threadIdx.x; i < FIN * HH; i += T)
        sW1[i] = W1[i];
    __syncthreads();

    int t    = blockIdx.x * T + threadIdx.x;
    int row  = t >> 1;
    int half = t & 1;
    if (row >= n) return;

    float acc[HH];
#pragma unroll
    for (int j = 0; j < HH; j++) acc[j] = 0.0f;

    const float4* xr = (const float4*)(x + (long long)row * FIN) + half * 16;
    const float*  w  = sW1 + half * 64 * HH;
#pragma unroll 8
    for (int k4 = 0; k4 < 16; k4++) {
        float4 xv = __ldg(&xr[k4]);
        int k = k4 * 4;
#pragma unroll
        for (int j = 0; j < HH; j++) {
            acc[j] += xv.x * w[(k + 0) * HH + j];
            acc[j] += xv.y * w[(k + 1) * HH + j];
            acc[j] += xv.z * w[(k + 2) * HH + j];
            acc[j] += xv.w * w[(k + 3) * HH + j];
        }
    }
#pragma unroll
    for (int j = 0; j < HH; j++)
        acc[j] += __shfl_xor_sync(0xffffffffu, acc[j], 1);

    float4* h4 = (float4*)(g_h    + (long long)row * HH);
    float4* a4 = (float4*)(g_acc1 + (long long)row * HH);
    float4 z = make_float4(0.f, 0.f, 0.f, 0.f);
#pragma unroll
    for (int q = 0; q < 2; q++) {
        int qq = half * 2 + q;
        h4[qq] = make_float4(acc[qq * 4 + 0], acc[qq * 4 + 1],
                             acc[qq * 4 + 2], acc[qq * 4 + 3]);
        a4[qq] = z;   // zero acc1 here (independent of counts)
    }
}

// 2) scale: dinv = rsqrt(cnt+1); hs = h*dinv (fp32 + fp16).  4 threads per node.
__global__ __launch_bounds__(T) void k_scale(int n) {
    int t   = blockIdx.x * T + threadIdx.x;
    int row = t >> 2;
    int q   = t & 3;
    if (row >= n) return;
    float di = rsqrtf((float)(g_cnt[row] + 1));
    if (q == 0) g_dinv[row] = di;
    float4 h = *((const float4*)(g_h + (long long)row * HH) + q);
    h.x *= di; h.y *= di; h.z *= di; h.w *= di;
    *((float4*)(g_hs + (long long)row * HH) + q) = h;
    __half2 p0 = __floats2half2_rn(h.x, h.y);
    __half2 p1 = __floats2half2_rn(h.z, h.w);
    *((__half2*)(g_hsh + (long long)row * HH) + q * 2 + 0) = p0;
    *((__half2*)(g_hsh + (long long)row * HH) + q * 2 + 1) = p1;
}

// 3) scatter layer 1: acc1[dst] += hs[src] — 4 threads per edge, fp16 gather,
//    fp32 vector RED. Gather is 8B/lane (one 32B row per edge -> 1 line visit);
//    RED is float4/lane (64B row -> 1 line visit).
__global__ __launch_bounds__(T) void k_scatter1(const int* __restrict__ ei, int e) {
    int gt    = blockIdx.x * T + threadIdx.x;
    int lane  = threadIdx.x & 31;
    int wbase = (gt >> 5) * 8;          // first edge of this warp
    int k = lane >> 2;                  // edge slot within warp (0..7)
    int q = lane & 3;                   // quarter of the 16-feature row

    // coalesced index loads: lanes 0-7 load 8 src, lanes 8-15 load 8 dst
    int idx = wbase + (lane & 7);
    int tmp = 0;
    if (lane < 16 && idx < e)
        tmp = (lane < 8) ? ei[idx] : ei[e + idx];
    int s = __shfl_sync(0xffffffffu, tmp, k);
    int d = __shfl_sync(0xffffffffu, tmp, 8 + k);

    int eb = wbase + k;
    if (eb >= e) return;
    if ((unsigned)s >= NN) s = 0;
    if ((unsigned)d >= NN) d = 0;

    // 8B fp16 gather -> fp32
    uint2 raw = __ldg((const uint2*)(g_hsh + (long long)s * HH) + q);
    __half2 h0 = *(__half2*)&raw.x;
    __half2 h1 = *(__half2*)&raw.y;
    float2 f0 = __half22float2(h0);
    float2 f1 = __half22float2(h1);
    float4 v = make_float4(f0.x, f0.y, f1.x, f1.y);
    atomicAdd((float4*)(g_acc1 + (long long)d * HH) + q, v);
}

// 4) layer-1 epilogue + GEMM2: out1 = relu(dinv*(acc1+hs) + b1);
//    gs = (out1 @ W2) * dinv; zero acc2
__global__ __launch_bounds__(T) void k_fin1_gemm2(const float* __restrict__ b1,
                                                  const float* __restrict__ W2,
                                                  int n) {
    __shared__ float sW2[HH * CC];
    __shared__ float sb1[HH];
    for (int i = threadIdx.x; i < HH * CC; i += T) sW2[i] = W2[i];
    for (int i = threadIdx.x; i < HH; i += T) sb1[i] = b1[i];
    __syncthreads();

    int row = blockIdx.x * T + threadIdx.x;
    if (row >= n) return;
    float di = g_dinv[row];

    const float4* ac4 = (const float4*)(g_acc1 + (long long)row * HH);
    const float4* hs4 = (const float4*)(g_hs + (long long)row * HH);
    float gc0 = 0.f, gc1 = 0.f;
#pragma unroll
    for (int q = 0; q < HH / 4; q++) {
        float4 a = ac4[q];
        float4 h = hs4[q];
        float o0 = fmaxf(di * (a.x + h.x) + sb1[q * 4 + 0], 0.f);
        float o1 = fmaxf(di * (a.y + h.y) + sb1[q * 4 + 1], 0.f);
        float o2 = fmaxf(di * (a.z + h.z) + sb1[q * 4 + 2], 0.f);
        float o3 = fmaxf(di * (a.w + h.w) + sb1[q * 4 + 3], 0.f);
        gc0 += o0 * sW2[(q * 4 + 0) * CC + 0] + o1 * sW2[(q * 4 + 1) * CC + 0]
             + o2 * sW2[(q * 4 + 2) * CC + 0] + o3 * sW2[(q * 4 + 3) * CC + 0];
        gc1 += o0 * sW2[(q * 4 + 0) * CC + 1] + o1 * sW2[(q * 4 + 1) * CC + 1]
             + o2 * sW2[(q * 4 + 2) * CC + 1] + o3 * sW2[(q * 4 + 3) * CC + 1];
    }
    *(float2*)(g_gs   + (long long)row * CC) = make_float2(gc0 * di, gc1 * di);
    *(float2*)(g_acc2 + (long long)row * CC) = make_float2(0.f, 0.f);
}

// 5) scatter layer 2: acc2[dst] += gs[src]  (float2 atomicAdd)
__global__ __launch_bounds__(T) void k_scatter2(const int* __restrict__ ei, int e) {
    int i = blockIdx.x * T + threadIdx.x;
    if (i >= e) return;
    int s = ei[i];
    int d = ei[e + i];
    if ((unsigned)s >= NN) s = 0;
    if ((unsigned)d >= NN) d = 0;
    float2 v = __ldg((const float2*)(g_gs + (long long)s * CC));
    atomicAdd((float2*)(g_acc2 + (long long)d * CC), v);
}

// 6) final: out = dinv*(acc2+gs) + b2; restore g_cnt zero-invariant
__global__ void k_final(const float* __restrict__ b2, float* __restrict__ out, int n) {
    int row = blockIdx.x * blockDim.x + threadIdx.x;
    if (row >= n) return;
    float di = g_dinv[row];
    float2 a = *((const float2*)(g_acc2 + (long long)row * CC));
    float2 h = *((const float2*)(g_gs + (long long)row * CC));
    float2 o;
    o.x = di * (a.x + h.x) + b2[0];
    o.y = di * (a.y + h.y) + b2[1];
    *((float2*)(out + (long long)row * CC)) = o;
    g_cnt[row] = 0;   // ready for next graph replay
}

extern "C" void kernel_launch(void* const* d_in, const int* in_sizes, int n_in,
                              void* d_out, int out_size) {
    const float* x  = (const float*)d_in[0];
    const int*   ei = (const int*)d_in[1];    // int32 (JAX x64 disabled)
    const float* W1 = (const float*)d_in[2];
    const float* b1 = (const float*)d_in[3];
    const float* W2 = (const float*)d_in[4];
    const float* b2 = (const float*)d_in[5];
    float* out = (float*)d_out;

    int n = in_sizes[0] / FIN;     // 100000
    int e = in_sizes[1] / 2;       // 3200000

    int gb_n  = (n + T - 1) / T;
    int gb_e  = (e + T - 1) / T;
    int gb_gemm  = (2 * n + T - 1) / T;              // 782
    int gb_cnt   = (e / 4 + T - 1) / T;              // 4 edges/thread
    int gb_fused = gb_gemm + gb_cnt;
    int gb_4n = (4 * n + T - 1) / T;
    int gb_4e = (int)(((long long)e * 4 + T - 1) / T);

    k_fused     <<<gb_fused, T>>>(x, W1, ei, n, e, gb_gemm);
    k_scale     <<<gb_4n, T>>>(n);
    k_scatter1  <<<gb_4e, T>>>(ei, e);
    k_fin1_gemm2<<<gb_n, T>>>(b1, W2, n);
    k_scatter2  <<<gb_e, T>>>(ei, e);
    k_final     <<<gb_n, T>>>(b2, out, n);
}